// round 3
// baseline (speedup 1.0000x reference)
#include <cuda_runtime.h>
#include <cstdint>

// Problem constants
#define Bn   4
#define Cn   16
#define Hn   800
#define Wn   1200
#define HWn  (Hn * Wn)          // 960000
#define HFn  200                 // H/4
#define WFn  200                 // W/6
#define DHn  512
#define DWn  512
#define NPIX (DHn * DWn)         // 262144

// Scratch: channels-last union atlas [B,H,W,16] and texture [B,H,W,4]
__device__ float4 g_union4[(size_t)Bn * HWn * 4];  // 245.76 MB
__device__ float4 g_tex4[(size_t)Bn * HWn];        //  61.44 MB

// Part -> source selection: parts {1, 14..21} come from source_feature
#define SRC_MASK 0x003FC002u
// Apparel classes: cls==2 or 15<=cls<=22  -> bits 2, 15..22
#define APP_MASK 0x007F8004u

// XLA lowering of  (x * 199) / 255 :
//   divide(t, 255) -> multiply(t, fl(1/255)), reciprocal constant-folded in f32
//   fl(1/255) bits = 0x3B808081.  The two multiplies are NOT reassociated.
__device__ __forceinline__ float recip255() {
    return __uint_as_float(0x3B808081u);
}

// ---------------------------------------------------------------------------
// Kernel A: build channels-last union atlas + channels-last texture.
// ---------------------------------------------------------------------------
__global__ __launch_bounds__(256) void k_build_atlas(
    const float* __restrict__ sf,   // source_feature [B,16,H,W]
    const float* __restrict__ tf,   // target_feature [B,16,H,W]
    const float* __restrict__ st)   // source_texture [B,3,H,W]
{
    const int b   = blockIdx.y;
    const int pos = blockIdx.x * 256 + threadIdx.x;   // 0 .. HWn-1

    const int h = pos / Wn;
    const int w = pos - h * Wn;
    const int part = (h / HFn) * 6 + (w / WFn);
    const bool use_src = (SRC_MASK >> part) & 1u;

    const float* fbase = (use_src ? sf : tf) + (size_t)b * Cn * HWn + pos;

    float v[16];
#pragma unroll
    for (int ch = 0; ch < 16; ch++)
        v[ch] = __ldg(fbase + (size_t)ch * HWn);

    float4* o = g_union4 + ((size_t)b * HWn + pos) * 4;
    o[0] = make_float4(v[0],  v[1],  v[2],  v[3]);
    o[1] = make_float4(v[4],  v[5],  v[6],  v[7]);
    o[2] = make_float4(v[8],  v[9],  v[10], v[11]);
    o[3] = make_float4(v[12], v[13], v[14], v[15]);

    const float* tb = st + (size_t)b * 3 * HWn + pos;
    g_tex4[(size_t)b * HWn + pos] =
        make_float4(__ldg(tb), __ldg(tb + HWn), __ldg(tb + 2 * HWn), 0.0f);
}

// ---------------------------------------------------------------------------
// Kernel B: per output pixel gather + composite.
// ---------------------------------------------------------------------------
__global__ __launch_bounds__(256) void k_render(
    const float* __restrict__ dp,    // dense_pose [B,DH,DW,3]
    const float* __restrict__ timg,  // target_image [B,3,DH,DW]
    float* __restrict__ out)         // [B,19,DH,DW]
{
    const int b   = blockIdx.y;
    const int pix = blockIdx.x * 256 + threadIdx.x;  // 0 .. NPIX-1

    const float* d = dp + ((size_t)b * NPIX + pix) * 3;
    const float clsf = d[0];
    const float U    = d[1];
    const float V    = d[2];

    const int  cls   = (int)clsf;
    const bool valid = (cls >= 1) && (V != 0.0f);

    int p = cls - 1;
    p = p < 0 ? 0 : (p > 23 ? 23 : p);

    const float R = recip255();
    // XLA: t = RN(U*199); ui = trunc(RN(t * fl(1/255)))  -- two separate muls
    const int ui = (int)__fmul_rn(__fmul_rn(U, 199.0f), R);
    const int vi = (int)__fmul_rn(__fmul_rn(__fsub_rn(255.0f, V), 199.0f), R);

    const int tr  = p / 6;
    const int tc  = p - tr * 6;
    const int pos = (tr * HFn + ui) * Wn + (tc * WFn + vi);

    float4 f0, f1, f2, f3, tx;
    if (valid) {
        const float4* u = g_union4 + ((size_t)b * HWn + pos) * 4;
        f0 = u[0]; f1 = u[1]; f2 = u[2]; f3 = u[3];
        tx = g_tex4[(size_t)b * HWn + pos];
    } else {
        f0 = f1 = f2 = f3 = make_float4(0.f, 0.f, 0.f, 0.f);
        tx = make_float4(0.f, 0.f, 0.f, 0.f);
    }

    float* ob = out + (size_t)b * 19 * NPIX + pix;
    ob[ 0 * NPIX] = f0.x;  ob[ 1 * NPIX] = f0.y;
    ob[ 2 * NPIX] = f0.z;  ob[ 3 * NPIX] = f0.w;
    ob[ 4 * NPIX] = f1.x;  ob[ 5 * NPIX] = f1.y;
    ob[ 6 * NPIX] = f1.z;  ob[ 7 * NPIX] = f1.w;
    ob[ 8 * NPIX] = f2.x;  ob[ 9 * NPIX] = f2.y;
    ob[10 * NPIX] = f2.z;  ob[11 * NPIX] = f2.w;
    ob[12 * NPIX] = f3.x;  ob[13 * NPIX] = f3.y;
    ob[14 * NPIX] = f3.z;  ob[15 * NPIX] = f3.w;

    const bool apparel = (APP_MASK >> cls) & 1u;   // implies cls!=0
    const float a = apparel ? 1.0f : 0.0f;
    const float i = (!apparel && cls != 0) ? 1.0f : 0.0f;

    const float* ti = timg + (size_t)b * 3 * NPIX + pix;
    ob[16 * NPIX] = tx.x * a + __ldg(ti)            * i;
    ob[17 * NPIX] = tx.y * a + __ldg(ti + NPIX)     * i;
    ob[18 * NPIX] = tx.z * a + __ldg(ti + 2 * NPIX) * i;
}

// ---------------------------------------------------------------------------
extern "C" void kernel_launch(void* const* d_in, const int* in_sizes, int n_in,
                              void* d_out, int out_size)
{
    const float* source_feature = (const float*)d_in[0];
    const float* target_feature = (const float*)d_in[1];
    const float* dense_pose     = (const float*)d_in[2];
    const float* source_texture = (const float*)d_in[3];
    const float* target_image   = (const float*)d_in[4];
    float* out = (float*)d_out;

    dim3 gA(HWn / 256, Bn);
    k_build_atlas<<<gA, 256>>>(source_feature, target_feature, source_texture);

    dim3 gB(NPIX / 256, Bn);
    k_render<<<gB, 256>>>(dense_pose, target_image, out);
}

// round 4
// speedup vs baseline: 1.3567x; 1.3567x over previous
#include <cuda_runtime.h>
#include <cstdint>

// Problem constants
#define Bn   4
#define Cn   16
#define Hn   800
#define Wn   1200
#define HWn  (Hn * Wn)          // 960000
#define HFn  200                 // H/4
#define WFn  200                 // W/6
#define NPIX (512 * 512)         // 262144

// Part -> source selection: parts {1, 14..21} come from source_feature
#define SRC_MASK 0x003FC002u
// Apparel classes: cls==2 or 15<=cls<=22  -> bits 2, 15..22
#define APP_MASK 0x007F8004u

// XLA lowering of (x*199)/255: divide -> multiply by fl(1/255) = 0x3B808081,
// multiplies NOT reassociated (verified bit-exact in R3).
__device__ __forceinline__ float recip255() {
    return __uint_as_float(0x3B808081u);
}

// ---------------------------------------------------------------------------
// Fused kernel: per output pixel, gather 16 feature channels + 3 texture
// channels directly from NCHW inputs, composite, write 19 output planes.
// No scratch atlas: compulsory DRAM traffic only.
// ---------------------------------------------------------------------------
__global__ __launch_bounds__(256) void k_fused(
    const float* __restrict__ sf,    // source_feature [B,16,H,W]
    const float* __restrict__ tf,    // target_feature [B,16,H,W]
    const float* __restrict__ dp,    // dense_pose [B,512,512,3]
    const float* __restrict__ st,    // source_texture [B,3,H,W]
    const float* __restrict__ timg,  // target_image [B,3,512,512]
    float* __restrict__ out)         // [B,19,512,512]
{
    const int b   = blockIdx.y;
    const int pix = blockIdx.x * 256 + threadIdx.x;   // 0 .. NPIX-1

    const float* d = dp + ((size_t)b * NPIX + pix) * 3;
    const float clsf = d[0];
    const float U    = d[1];
    const float V    = d[2];

    const int  cls   = (int)clsf;
    const bool valid = (cls >= 1) && (V != 0.0f);

    int p = cls - 1;
    p = p < 0 ? 0 : (p > 23 ? 23 : p);

    const float R = recip255();
    // XLA: t = RN(x*199); idx = trunc(RN(t * fl(1/255)))
    const int ui = (int)__fmul_rn(__fmul_rn(U, 199.0f), R);
    const int vi = (int)__fmul_rn(__fmul_rn(__fsub_rn(255.0f, V), 199.0f), R);

    const int tr  = p / 6;
    const int tc  = p - tr * 6;
    const int pos = (tr * HFn + ui) * Wn + (tc * WFn + vi);

    // Union selection: which tensor does this PART come from
    const bool use_src = (SRC_MASK >> p) & 1u;
    const float* fbase = (use_src ? sf : tf) + (size_t)b * Cn * HWn + pos;

    float v[16];
    if (valid) {
#pragma unroll
        for (int ch = 0; ch < 16; ch++)
            v[ch] = __ldg(fbase + (size_t)ch * HWn);
    } else {
#pragma unroll
        for (int ch = 0; ch < 16; ch++)
            v[ch] = 0.0f;
    }

    const bool apparel = (APP_MASK >> cls) & 1u;   // implies cls != 0
    const bool bg      = (cls != 0);

    // Texture gather only matters when apparel & valid
    float t0 = 0.f, t1 = 0.f, t2 = 0.f;
    if (apparel && valid) {
        const float* tb = st + (size_t)b * 3 * HWn + pos;
        t0 = __ldg(tb);
        t1 = __ldg(tb + HWn);
        t2 = __ldg(tb + 2 * HWn);
    }

    float* ob = out + (size_t)b * 19 * NPIX + pix;
#pragma unroll
    for (int ch = 0; ch < 16; ch++)
        ob[(size_t)ch * NPIX] = v[ch];

    if (apparel) {
        ob[16 * NPIX] = t0;
        ob[17 * NPIX] = t1;
        ob[18 * NPIX] = t2;
    } else if (bg) {
        const float* ti = timg + (size_t)b * 3 * NPIX + pix;
        ob[16 * NPIX] = __ldg(ti);
        ob[17 * NPIX] = __ldg(ti + NPIX);
        ob[18 * NPIX] = __ldg(ti + 2 * NPIX);
    } else {
        ob[16 * NPIX] = 0.0f;
        ob[17 * NPIX] = 0.0f;
        ob[18 * NPIX] = 0.0f;
    }
}

// ---------------------------------------------------------------------------
extern "C" void kernel_launch(void* const* d_in, const int* in_sizes, int n_in,
                              void* d_out, int out_size)
{
    const float* source_feature = (const float*)d_in[0];
    const float* target_feature = (const float*)d_in[1];
    const float* dense_pose     = (const float*)d_in[2];
    const float* source_texture = (const float*)d_in[3];
    const float* target_image   = (const float*)d_in[4];
    float* out = (float*)d_out;

    dim3 g(NPIX / 256, Bn);
    k_fused<<<g, 256>>>(source_feature, target_feature, dense_pose,
                        source_texture, target_image, out);
}